// round 6
// baseline (speedup 1.0000x reference)
#include <cuda_runtime.h>

// GraphPyramidPooling — adjacency (d_in[0]) is dead code. Live math:
//   s0_i = sig(h_i·w0+b0); s1 = sig(s0*(h·w1)+b1); s2 = sig(s0*s1*(h·w2)+b2)
//   (uses s*(h·w) == (h*s)·w up to fp rounding, ~1e-7 << 1e-3 tol)
//   out[r] = a0[r]*h[r] + g1[r]*h[src1[r]] + g2[r]*h[src2[r]]
// with exact stable top-k ranks per level via u64 keys (bits(s)<<32 | ~idx).
//
// R5: per-launch fixed cost (~5-7us/kernel on this pipeline) dominates, so
// everything is ONE persistent kernel (296 co-resident blocks) with a
// software grid barrier between the 5 phases.

#define D    512
#define DV   128
#define N0   4096
#define K0   3276
#define N1   3276
#define K1   1965
#define N2   1965
#define K2   786
#define NP0  4096
#define NP1  3328
#define NP2  1984
#define NB   296
#define NTH  256
#define NWARP (NB * 8)

typedef unsigned long long u64;
typedef unsigned int u32;

__device__ u64   g_k0[NP0];
__device__ u64   g_k1[NP1];
__device__ u64   g_k2[NP2];
__device__ float g_s0a[N0];
__device__ float g_d1[N0];
__device__ float g_d2[N0];
__device__ float g_a0[N0];
__device__ float g_g1[N0];
__device__ float g_g2[N0];
__device__ int   g_src1[N0];
__device__ int   g_src2[N0];
__device__ int   g_inv0[N1];
__device__ int   g_p2src[N2];
__device__ float g_p2gain[N2];
__device__ unsigned g_bar;    // monotonic arrival counter (never reset)
__device__ unsigned g_epoch;  // launches completed; base = epoch*4*NB

__device__ __forceinline__ float warp_sum(float v) {
#pragma unroll
    for (int o = 16; o; o >>= 1) v += __shfl_xor_sync(0xffffffffu, v, o);
    return v;
}
__device__ __forceinline__ float sigmoidf(float x) {
    return 1.0f / (1.0f + expf(-x));
}
__device__ __forceinline__ u64 make_key(float s, int idx) {
    return ((u64)(u32)__float_as_int(s) << 32) | (u32)(~(u32)idx);
}
__device__ __forceinline__ float key_score(u64 k) {
    return __int_as_float((int)(k >> 32));
}

// Software grid barrier: all NB blocks are co-resident (2/SM worst case).
// Monotonic counter + wrap-safe compare; epoch gives the per-launch base.
__device__ __forceinline__ void grid_barrier(unsigned target) {
    __syncthreads();
    if (threadIdx.x == 0) {
        __threadfence();
        atomicAdd(&g_bar, 1u);
        unsigned v;
        do {
            asm volatile("ld.acquire.gpu.u32 %0, [%1];"
                         : "=r"(v) : "l"(&g_bar) : "memory");
        } while ((int)(v - target) < 0);
    }
    __syncthreads();
}

// One rank stage: stage level keys into smem, every warp ranks its rows
// against the whole array (exact stable: strict u64 >), lane 0 chains the
// per-row scalars for the next level.
template <int LVL, int NN, int NPAD, int KK>
__device__ void rank_phase(u64* smk, const float* __restrict__ b) {
    const u64* gk = (LVL == 0) ? g_k0 : (LVL == 1) ? g_k1 : g_k2;
    for (int t = threadIdx.x; t < NPAD; t += NTH)
        smk[t] = (t < NN) ? gk[t] : 0ULL;   // pad 0 < every real key
    __syncthreads();

    const int wid  = threadIdx.x >> 5;
    const int lane = threadIdx.x & 31;
    const int gw   = blockIdx.x * 8 + wid;
    const int i1 = gw, i2 = gw + NWARP;

    u64 ka = (i1 < NN) ? smk[i1] : ~0ULL;
    u64 kb = (i2 < NN) ? smk[i2] : ~0ULL;
    int ca = 0, cb = 0;
    const ulonglong2* s2 = (const ulonglong2*)smk;
#pragma unroll 4
    for (int q = lane; q < NPAD / 2; q += 32) {
        ulonglong2 v = s2[q];
        ca += (int)(v.x > ka) + (int)(v.y > ka);
        cb += (int)(v.x > kb) + (int)(v.y > kb);
    }
    int packed = ca | (cb << 16);
#pragma unroll
    for (int o = 16; o; o >>= 1) packed += __shfl_xor_sync(0xffffffffu, packed, o);
    if (lane != 0) return;

#pragma unroll
    for (int t = 0; t < 2; t++) {
        const int i = (t == 0) ? i1 : i2;
        if (i >= NN) continue;
        const int rank = (t == 0) ? (packed & 0xFFFF) : (packed >> 16);
        const bool sel = rank < KK;
        const u64  ki  = (t == 0) ? ka : kb;
        if (LVL == 0) {
            float s0 = key_score(ki);
            g_a0[i] = sel ? s0 : 0.f;
            if (sel) {
                float s1 = sigmoidf(s0 * g_d1[i] + b[1]);
                g_k1[rank]   = make_key(s1, rank);
                g_inv0[rank] = i;
            }
        } else if (LVL == 1) {
            int   src  = g_inv0[i];
            float s1   = key_score(ki);
            float gain = g_s0a[src] * s1;
            g_g1[i]   = sel ? gain : 0.f;
            g_src1[i] = src;
            if (sel) {
                float s2v = sigmoidf(gain * g_d2[src] + b[2]);
                g_k2[rank]     = make_key(s2v, rank);
                g_p2src[rank]  = src;
                g_p2gain[rank] = gain;
            }
        } else {
            float s2v = key_score(ki);
            g_g2[i]   = sel ? g_p2gain[i] * s2v : 0.f;
            g_src2[i] = g_p2src[i];
        }
    }
}

__global__ void __launch_bounds__(NTH)
mega_kernel(const float* __restrict__ h, const float* __restrict__ W,
            const float* __restrict__ b, float* __restrict__ out) {
    __shared__ __align__(16) u64 smk[NP0];   // 32KB, reused per phase
    const int tid  = threadIdx.x;
    const int wid  = tid >> 5;
    const int lane = tid & 31;
    const int gw   = blockIdx.x * 8 + wid;
    const unsigned base = g_epoch * (4u * NB);  // read before any arrival

    // ---- phase 0: three dot products per row + key0 + tail inits ----
    for (int r = gw; r < N0; r += NWARP) {
        const float4* hr = (const float4*)h + (size_t)r * DV;
        const float4* w0 = (const float4*)W;
        const float4* w1 = w0 + DV;
        const float4* w2 = w0 + 2 * DV;
        float a0 = 0.f, a1 = 0.f, a2 = 0.f;
#pragma unroll
        for (int i = 0; i < 4; i++) {
            float4 a  = __ldg(hr + lane + 32 * i);
            float4 c0 = __ldg(w0 + lane + 32 * i);
            float4 c1 = __ldg(w1 + lane + 32 * i);
            float4 c2 = __ldg(w2 + lane + 32 * i);
            a0 += a.x * c0.x + a.y * c0.y + a.z * c0.z + a.w * c0.w;
            a1 += a.x * c1.x + a.y * c1.y + a.z * c1.z + a.w * c1.w;
            a2 += a.x * c2.x + a.y * c2.y + a.z * c2.z + a.w * c2.w;
        }
        a0 = warp_sum(a0); a1 = warp_sum(a1); a2 = warp_sum(a2);
        if (lane == 0) {
            float s0 = sigmoidf(a0 + b[0]);
            g_s0a[r] = s0;
            g_k0[r]  = make_key(s0, r);
            g_d1[r]  = a1;
            g_d2[r]  = a2;
            if (r >= N1) { g_g1[r] = 0.f; g_src1[r] = r; }
            if (r >= N2) { g_g2[r] = 0.f; g_src2[r] = r; }
        }
    }
    grid_barrier(base + 1u * NB);

    // ---- phases 1-3: exact stable ranks, scalar chaining ----
    rank_phase<0, N0, NP0, K0>(smk, b);
    grid_barrier(base + 2u * NB);
    rank_phase<1, N1, NP1, K1>(smk, b);
    grid_barrier(base + 3u * NB);
    rank_phase<2, N2, NP2, K2>(smk, b);
    grid_barrier(base + 4u * NB);

    // ---- phase 4: out[r] = a0*h[r] + g1*h[src1] + g2*h[src2] ----
    const float4* h4 = (const float4*)h;
    for (int i = blockIdx.x * NTH + tid; i < N0 * DV; i += NB * NTH) {
        int r = i >> 7;
        int c = i & 127;
        float a0 = g_a0[r];
        float g1 = g_g1[r];
        float g2 = g_g2[r];
        int   s1 = g_src1[r];
        int   s2 = g_src2[r];
        float4 v0 = __ldg(h4 + (size_t)r  * DV + c);
        float4 v1 = __ldg(h4 + (size_t)s1 * DV + c);
        float4 v2 = __ldg(h4 + (size_t)s2 * DV + c);
        float4 o;
        o.x = a0 * v0.x + g1 * v1.x + g2 * v2.x;
        o.y = a0 * v0.y + g1 * v1.y + g2 * v2.y;
        o.z = a0 * v0.z + g1 * v1.z + g2 * v2.z;
        o.w = a0 * v0.w + g1 * v1.w + g2 * v2.w;
        ((float4*)out)[i] = o;
    }

    // advance epoch for the next launch (launches are serialized)
    if (blockIdx.x == 0 && tid == 0) {
        __threadfence();
        g_epoch = g_epoch + 1u;
    }
}

extern "C" void kernel_launch(void* const* d_in, const int* in_sizes, int n_in,
                              void* d_out, int out_size) {
    // inputs: [0]=g (UNUSED), [1]=h [4096,512], [2]=W [3,512], [3]=b [3]
    const float* h = (const float*)d_in[1];
    const float* W = (const float*)d_in[2];
    const float* b = (const float*)d_in[3];
    float* out = (float*)d_out;
    mega_kernel<<<NB, NTH>>>(h, W, b, out);
}